// round 2
// baseline (speedup 1.0000x reference)
#include <cuda_runtime.h>
#include <cstdint>

// ---------------- problem constants ----------------
#define NB 16
#define NT 1024
#define NF 512
#define NG 2
#define NV 320
#define ND 128
#define NTOK (NB*NT)        // 16384
#define NJ (NG*NV)          // 640

// ---------------- device scratch (no cudaMalloc allowed) ----------------
__device__ float g_logits[(size_t)NTOK * NJ];     // 40 MB
__device__ float g_counts[NT * NG * NV];          // (t,g,v) hard counts
__device__ float g_avg[NG * NV];                  // sum of softmax probs

// ---------------- zero / init kernel ----------------
__global__ void zero_kernel(float* out_scalars) {
    int i = blockIdx.x * blockDim.x + threadIdx.x;
    if (i < NT * NG * NV) g_counts[i] = 0.f;
    if (i < NG * NV) g_avg[i] = 0.f;
    if (i < 2) out_scalars[i] = 0.f;
}

// ---------------- fp32 GEMM: C[n,j] = sum_f X[n,f]*W[j,f] + b[j] ----------------
// BM=128, BN=64, BK=32, 256 threads, per-thread 8x4 via packed f32x2 FMAs.
#define BM 128
#define BN 64
#define BK 32

__global__ __launch_bounds__(256) void gemm_kernel(
    const float* __restrict__ X, const float* __restrict__ W,
    const float* __restrict__ bias)
{
    __shared__ float As[BK][BM + 4];   // transposed: As[k][m]
    __shared__ float Bs[BK][BN + 4];   // transposed: Bs[k][j]

    const int tid = threadIdx.x;
    const int tx = tid & 15;          // 0..15 -> 4 cols each
    const int ty = tid >> 4;          // 0..15 -> 8 rows each
    const int rowBase = blockIdx.y * BM;
    const int colBase = blockIdx.x * BN;

    const int lr = tid >> 3;          // 0..31
    const int lk = (tid & 7) * 4;     // 0,4,...,28

    unsigned long long acc[4][4];     // acc[i2][j] = f32x2 (row 2*i2, row 2*i2+1)
    #pragma unroll
    for (int i = 0; i < 4; i++)
        #pragma unroll
        for (int j = 0; j < 4; j++) acc[i][j] = 0ULL;

    for (int kk = 0; kk < NF; kk += BK) {
        // load X tile (128 x 32)
        #pragma unroll
        for (int r = 0; r < 4; r++) {
            int row = lr + r * 32;
            float4 v = *(const float4*)(X + (size_t)(rowBase + row) * NF + kk + lk);
            As[lk + 0][row] = v.x; As[lk + 1][row] = v.y;
            As[lk + 2][row] = v.z; As[lk + 3][row] = v.w;
        }
        // load W tile (64 x 32)
        #pragma unroll
        for (int r = 0; r < 2; r++) {
            int j = lr + r * 32;
            float4 v = *(const float4*)(W + (size_t)(colBase + j) * NF + kk + lk);
            Bs[lk + 0][j] = v.x; Bs[lk + 1][j] = v.y;
            Bs[lk + 2][j] = v.z; Bs[lk + 3][j] = v.w;
        }
        __syncthreads();

        #pragma unroll
        for (int k = 0; k < BK; k++) {
            // a pairs: 8 consecutive floats -> 4 packed f32x2 (aligned 16B loads)
            ulonglong2 la0 = *(const ulonglong2*)&As[k][ty * 8];
            ulonglong2 la1 = *(const ulonglong2*)&As[k][ty * 8 + 4];
            unsigned long long a2[4] = { la0.x, la0.y, la1.x, la1.y };
            float4 bv = *(const float4*)&Bs[k][tx * 4];
            unsigned long long b2[4];
            asm("mov.b64 %0, {%1,%1};" : "=l"(b2[0]) : "r"(__float_as_uint(bv.x)));
            asm("mov.b64 %0, {%1,%1};" : "=l"(b2[1]) : "r"(__float_as_uint(bv.y)));
            asm("mov.b64 %0, {%1,%1};" : "=l"(b2[2]) : "r"(__float_as_uint(bv.z)));
            asm("mov.b64 %0, {%1,%1};" : "=l"(b2[3]) : "r"(__float_as_uint(bv.w)));
            #pragma unroll
            for (int i2 = 0; i2 < 4; i2++)
                #pragma unroll
                for (int j = 0; j < 4; j++)
                    asm("fma.rn.f32x2 %0, %1, %2, %0;"
                        : "+l"(acc[i2][j]) : "l"(a2[i2]), "l"(b2[j]));
        }
        __syncthreads();
    }

    // epilogue: add bias, store
    const int col0 = colBase + tx * 4;
    float4 bv = *(const float4*)(bias + col0);
    #pragma unroll
    for (int i2 = 0; i2 < 4; i2++) {
        unsigned int lo[4], hi[4];
        #pragma unroll
        for (int j = 0; j < 4; j++)
            asm("mov.b64 {%0,%1}, %2;" : "=r"(lo[j]), "=r"(hi[j]) : "l"(acc[i2][j]));
        int row = rowBase + ty * 8 + i2 * 2;
        float4 o0 = make_float4(__uint_as_float(lo[0]) + bv.x,
                                __uint_as_float(lo[1]) + bv.y,
                                __uint_as_float(lo[2]) + bv.z,
                                __uint_as_float(lo[3]) + bv.w);
        float4 o1 = make_float4(__uint_as_float(hi[0]) + bv.x,
                                __uint_as_float(hi[1]) + bv.y,
                                __uint_as_float(hi[2]) + bv.z,
                                __uint_as_float(hi[3]) + bv.w);
        *(float4*)(g_logits + (size_t)row * NJ + col0) = o0;
        *(float4*)(g_logits + (size_t)(row + 1) * NJ + col0) = o1;
    }
}

// ---------------- fused epilogue: argmax / softmax-accum / gather ----------------
// One warp handles one (token, group). 8 warps/block, 16 iterations -> 128 tasks/block.
__global__ __launch_bounds__(256) void epilogue_kernel(
    const float* __restrict__ gumbel, const float* __restrict__ codebook,
    float* __restrict__ out)
{
    __shared__ float sAvg[8][NV];   // warp-private softmax-prob accumulators

    const int tid = threadIdx.x;
    const int wid = tid >> 5;
    const int lane = tid & 31;
    const int g = wid & 1;

    for (int i = tid; i < 8 * NV; i += 256) ((float*)sAvg)[i] = 0.f;
    __syncthreads();

    for (int it = 0; it < 16; it++) {
        int task = blockIdx.x * 128 + it * 8 + wid;   // 0..32767
        int n = task >> 1;                             // token index (g == task&1 == wid&1)
        const float* lrow = g_logits + (size_t)n * NJ + g * NV;
        const float* grow = gumbel  + (size_t)n * NJ + g * NV;

        float l[10];
        float bestL = -3.402823466e38f; int k1 = 0;
        float bestG = -3.402823466e38f; int k2 = 0;
        #pragma unroll
        for (int i = 0; i < 10; i++) {
            int v = lane + i * 32;
            float lv = lrow[v];
            l[i] = lv;
            float lg = lv + grow[v];
            if (lv > bestL) { bestL = lv; k1 = v; }
            if (lg > bestG) { bestG = lg; k2 = v; }
        }
        // warp argmax (lowest index on ties, matching jnp.argmax)
        #pragma unroll
        for (int off = 16; off; off >>= 1) {
            float oL = __shfl_xor_sync(0xffffffffu, bestL, off);
            int   oi = __shfl_xor_sync(0xffffffffu, k1,   off);
            if (oL > bestL || (oL == bestL && oi < k1)) { bestL = oL; k1 = oi; }
            float oG = __shfl_xor_sync(0xffffffffu, bestG, off);
            int   oj = __shfl_xor_sync(0xffffffffu, k2,   off);
            if (oG > bestG || (oG == bestG && oj < k2)) { bestG = oG; k2 = oj; }
        }
        // softmax over this group's 320 logits; accumulate probs
        float s = 0.f;
        #pragma unroll
        for (int i = 0; i < 10; i++) { l[i] = __expf(l[i] - bestL); s += l[i]; }
        #pragma unroll
        for (int off = 16; off; off >>= 1) s += __shfl_xor_sync(0xffffffffu, s, off);
        float inv = 1.0f / s;
        #pragma unroll
        for (int i = 0; i < 10; i++) sAvg[wid][lane + i * 32] += l[i] * inv;

        // hard one-hot count for code perplexity: counts[t][g][k1] += 1
        if (lane == 0)
            atomicAdd(&g_counts[((n & (NT - 1)) * NG + g) * NV + k1], 1.0f);

        // quantized output: gather codebook row k2 (argmax of logits+gumbel)
        float4 cb = ((const float4*)(codebook + (size_t)(g * NV + k2) * ND))[lane];
        ((float4*)(out + (size_t)n * (NG * ND) + g * ND))[lane] = cb;
    }

    __syncthreads();
    // reduce warp-private prob accumulators -> global
    for (int x = tid; x < NG * NV; x += 256) {
        int gg = x / NV, v = x - gg * NV;
        float s = sAvg[gg][v] + sAvg[gg + 2][v] + sAvg[gg + 4][v] + sAvg[gg + 6][v];
        atomicAdd(&g_avg[x], s);
    }
}

// ---------------- perplexity reduction ----------------
// mode 0: rows of g_counts (scale 1/NB) -> out[0] (code perplexity)
// mode 1: rows of g_avg (scale 1/NTOK) -> out[1] (prob perplexity)
// Device symbols are selected INSIDE device code (host cannot take their address).
__global__ __launch_bounds__(320) void perp_kernel(
    int mode, float scale, float* __restrict__ out)
{
    const float* vals = (mode == 0) ? g_counts : g_avg;
    const int tid = threadIdx.x;
    float p = vals[(size_t)blockIdx.x * NV + tid] * scale;
    float term = p * logf(p + 1e-7f);
    #pragma unroll
    for (int off = 16; off; off >>= 1) term += __shfl_xor_sync(0xffffffffu, term, off);
    __shared__ float red[10];
    if ((tid & 31) == 0) red[tid >> 5] = term;
    __syncthreads();
    if (tid == 0) {
        float s2 = red[0];
        #pragma unroll
        for (int i = 1; i < 10; i++) s2 += red[i];
        atomicAdd(out + mode, expf(-s2));
    }
}

// ---------------- launch ----------------
extern "C" void kernel_launch(void* const* d_in, const int* in_sizes, int n_in,
                              void* d_out, int out_size)
{
    const float* x        = (const float*)d_in[0];  // (16,1024,512)
    const float* w_proj   = (const float*)d_in[1];  // (640,512)
    const float* b_proj   = (const float*)d_in[2];  // (640)
    const float* codebook = (const float*)d_in[3];  // (1,640,128)
    const float* gumbel   = (const float*)d_in[4];  // (16384,2,320)
    float* out = (float*)d_out;
    float* scalars = out + (out_size - 2);          // [code_perp, prob_perp]

    zero_kernel<<<(NT * NG * NV + 255) / 256, 256>>>(scalars);

    dim3 ggrid(NJ / BN, NTOK / BM);                 // (10, 128)
    gemm_kernel<<<ggrid, 256>>>(x, w_proj, b_proj);

    epilogue_kernel<<<256, 256>>>(gumbel, codebook, out);

    perp_kernel<<<NT * NG, 320>>>(0, 1.0f / NB, scalars);          // code perplexity
    perp_kernel<<<NG, 320>>>(1, 1.0f / (float)NTOK, scalars);      // prob perplexity
}

// round 4
// speedup vs baseline: 1.8111x; 1.8111x over previous
#include <cuda_runtime.h>
#include <cuda_fp16.h>
#include <cstdint>

// ---------------- problem constants ----------------
#define NB 16
#define NT 1024
#define NF 512
#define NG 2
#define NV 320
#define ND 128
#define NTOK (NB*NT)        // 16384
#define NJ (NG*NV)          // 640

// ---------------- device scratch (no cudaMalloc allowed) ----------------
__device__ __half g_x0[(size_t)NTOK * NF];   // 16 MB
__device__ __half g_x1[(size_t)NTOK * NF];   // 16 MB
__device__ __half g_w0[(size_t)NJ * NF];
__device__ __half g_w1[(size_t)NJ * NF];
__device__ float g_logits[(size_t)NTOK * NJ];  // 40 MB
__device__ float g_counts[NT * NG * NV];
__device__ float g_avg[NG * NV];

// ---------------- helpers ----------------
__device__ __forceinline__ uint32_t smem_u32(const void* p) {
    uint32_t a;
    asm("{ .reg .u64 t; cvta.to.shared.u64 t, %1; cvt.u32.u64 %0, t; }" : "=r"(a) : "l"(p));
    return a;
}
#define SW128(b) ((b) ^ (((b) >> 3) & 0x70))
#define CP_ASYNC16(s, g) \
    asm volatile("cp.async.cg.shared.global [%0], [%1], 16;" :: "r"(s), "l"(g))
#define CP_COMMIT() asm volatile("cp.async.commit_group;" ::: "memory")
#define CP_WAIT(n)  asm volatile("cp.async.wait_group %0;" :: "n"(n) : "memory")
#define LDSM_X4(r0, r1, r2, r3, addr) \
    asm volatile("ldmatrix.sync.aligned.m8n8.x4.shared.b16 {%0,%1,%2,%3}, [%4];" \
        : "=r"(r0), "=r"(r1), "=r"(r2), "=r"(r3) : "r"(addr))
#define MMA16816(c, a0, a1, a2, a3, b0, b1) \
    asm volatile("mma.sync.aligned.m16n8k16.row.col.f32.f16.f16.f32 " \
        "{%0,%1,%2,%3}, {%4,%5,%6,%7}, {%8,%9}, {%0,%1,%2,%3};" \
        : "+f"((c)[0]), "+f"((c)[1]), "+f"((c)[2]), "+f"((c)[3]) \
        : "r"(a0), "r"(a1), "r"(a2), "r"(a3), "r"(b0), "r"(b1))

// ---------------- zero kernel ----------------
__global__ void zero_kernel(float* out_scalars) {
    int i = blockIdx.x * blockDim.x + threadIdx.x;
    if (i < NT * NG * NV) g_counts[i] = 0.f;
    if (i < NG * NV) g_avg[i] = 0.f;
    if (i < 2) out_scalars[i] = 0.f;
}

// ---------------- fp32 -> fp16 two-term split ----------------
__global__ __launch_bounds__(256) void split_kernel(const float4* __restrict__ src, int n4, int which) {
    int i = blockIdx.x * blockDim.x + threadIdx.x;
    if (i >= n4) return;
    __half2* d0 = which ? (__half2*)g_w0 : (__half2*)g_x0;
    __half2* d1 = which ? (__half2*)g_w1 : (__half2*)g_x1;
    float4 v = src[i];
    __half hx = __float2half_rn(v.x), hy = __float2half_rn(v.y);
    __half hz = __float2half_rn(v.z), hw = __float2half_rn(v.w);
    float rx = v.x - __half2float(hx), ry = v.y - __half2float(hy);
    float rz = v.z - __half2float(hz), rw = v.w - __half2float(hw);
    d0[2*i]   = __halves2half2(hx, hy);
    d0[2*i+1] = __halves2half2(hz, hw);
    d1[2*i]   = __halves2half2(__float2half_rn(rx), __float2half_rn(ry));
    d1[2*i+1] = __halves2half2(__float2half_rn(rz), __float2half_rn(rw));
}

// ---------------- HMMA GEMM: logits = x*W^T + b via 3-pass fp16 split ----------------
// BM=128 BN=64 BK=64(half), 3-stage cp.async pipeline, SW128 swizzle, 8 warps (4Mx2N).
#define STAGES 3
#define STG_A 16384                 // 128 rows x 128B
#define STG_B 8192                  // 64 rows x 128B
#define STG_BYTES (STG_A + STG_B)   // 24576
#define GEMM_SMEM (STAGES * STG_BYTES)

__global__ __launch_bounds__(256, 2) void gemm_mma_kernel(const float* __restrict__ bias)
{
    extern __shared__ __align__(1024) char smem[];
    const uint32_t sb = smem_u32(smem);
    const int tid = threadIdx.x, lane = tid & 31, wid = tid >> 5;
    const int wm = (wid & 3) * 32;       // warp m offset in tile
    const int wn = (wid >> 2) * 32;      // warp n offset in tile
    const int m0 = blockIdx.y * 128;
    const int j0 = blockIdx.x * 64;

    float acc[2][4][4];
    #pragma unroll
    for (int mt = 0; mt < 2; mt++)
        #pragma unroll
        for (int nt = 0; nt < 4; nt++)
            #pragma unroll
            for (int c = 0; c < 4; c++) acc[mt][nt][c] = 0.f;

    // per-thread load coordinates (16B chunks)
    const int arL = tid >> 3, auL = tid & 7;     // +n*256 rows step 32

    // ---- stage loader ----
    auto load_stage = [&](int s, int it) {
        const __half* Ag = (it < 16) ? g_x0 : g_x1;
        const __half* Bg = (it >= 8 && it < 16) ? g_w1 : g_w0;
        const int kk = (it & 7) * 64;
        const uint32_t stA = sb + s * STG_BYTES;
        const uint32_t stB = stA + STG_A;
        #pragma unroll
        for (int n = 0; n < 4; n++) {             // A: 1024 chunks
            int r = arL + n * 32, u = auL;
            uint32_t dst = stA + SW128(r * 128 + u * 16);
            CP_ASYNC16(dst, (const void*)(Ag + (size_t)(m0 + r) * NF + kk + u * 8));
        }
        #pragma unroll
        for (int n = 0; n < 2; n++) {             // B: 512 chunks
            int r = arL + n * 32, u = auL;
            uint32_t dst = stB + SW128(r * 128 + u * 16);
            CP_ASYNC16(dst, (const void*)(Bg + (size_t)(j0 + r) * NF + kk + u * 8));
        }
        CP_COMMIT();
    };

    load_stage(0, 0);
    load_stage(1, 1);

    for (int it = 0; it < 24; it++) {
        CP_WAIT(1);
        __syncthreads();
        const int s = it % STAGES;
        const uint32_t stA = sb + s * STG_BYTES;
        const uint32_t stB = stA + STG_A;
        #pragma unroll
        for (int ks = 0; ks < 4; ks++) {
            uint32_t a[2][4], b[2][4];
            #pragma unroll
            for (int mt = 0; mt < 2; mt++) {
                uint32_t off = (uint32_t)(wm + mt * 16 + (lane & 15)) * 128 + ks * 32 + (lane >> 4) * 16;
                LDSM_X4(a[mt][0], a[mt][1], a[mt][2], a[mt][3], stA + SW128(off));
            }
            #pragma unroll
            for (int nt2 = 0; nt2 < 2; nt2++) {
                uint32_t off = (uint32_t)(wn + nt2 * 16 + (lane & 15)) * 128 + ks * 32 + (lane >> 4) * 16;
                LDSM_X4(b[nt2][0], b[nt2][1], b[nt2][2], b[nt2][3], stB + SW128(off));
            }
            #pragma unroll
            for (int mt = 0; mt < 2; mt++)
                #pragma unroll
                for (int nt = 0; nt < 4; nt++)
                    MMA16816(acc[mt][nt], a[mt][0], a[mt][1], a[mt][2], a[mt][3],
                             b[nt >> 1][nt & 1], b[nt >> 1][(nt & 1) + 2]);
        }
        __syncthreads();
        if (it + 2 < 24) load_stage((it + 2) % STAGES, it + 2);
    }

    // ---- store: add bias, write logits ----
    #pragma unroll
    for (int mt = 0; mt < 2; mt++) {
        #pragma unroll
        for (int nt = 0; nt < 4; nt++) {
            int row = m0 + wm + mt * 16 + (lane >> 2);
            int col = j0 + wn + nt * 8 + (lane & 3) * 2;
            float2 bv = *(const float2*)(bias + col);
            float2 o0 = make_float2(acc[mt][nt][0] + bv.x, acc[mt][nt][1] + bv.y);
            float2 o1 = make_float2(acc[mt][nt][2] + bv.x, acc[mt][nt][3] + bv.y);
            *(float2*)(g_logits + (size_t)row * NJ + col) = o0;
            *(float2*)(g_logits + (size_t)(row + 8) * NJ + col) = o1;
        }
    }
}

// ---------------- fused epilogue (proven in R2) ----------------
__global__ __launch_bounds__(256) void epilogue_kernel(
    const float* __restrict__ gumbel, const float* __restrict__ codebook,
    float* __restrict__ out)
{
    __shared__ float sAvg[8][NV];

    const int tid = threadIdx.x;
    const int wid = tid >> 5;
    const int lane = tid & 31;
    const int g = wid & 1;

    for (int i = tid; i < 8 * NV; i += 256) ((float*)sAvg)[i] = 0.f;
    __syncthreads();

    for (int it = 0; it < 16; it++) {
        int task = blockIdx.x * 128 + it * 8 + wid;
        int n = task >> 1;
        const float* lrow = g_logits + (size_t)n * NJ + g * NV;
        const float* grow = gumbel  + (size_t)n * NJ + g * NV;

        float l[10];
        float bestL = -3.402823466e38f; int k1 = 0;
        float bestG = -3.402823466e38f; int k2 = 0;
        #pragma unroll
        for (int i = 0; i < 10; i++) {
            int v = lane + i * 32;
            float lv = lrow[v];
            l[i] = lv;
            float lg = lv + grow[v];
            if (lv > bestL) { bestL = lv; k1 = v; }
            if (lg > bestG) { bestG = lg; k2 = v; }
        }
        #pragma unroll
        for (int off = 16; off; off >>= 1) {
            float oL = __shfl_xor_sync(0xffffffffu, bestL, off);
            int   oi = __shfl_xor_sync(0xffffffffu, k1,   off);
            if (oL > bestL || (oL == bestL && oi < k1)) { bestL = oL; k1 = oi; }
            float oG = __shfl_xor_sync(0xffffffffu, bestG, off);
            int   oj = __shfl_xor_sync(0xffffffffu, k2,   off);
            if (oG > bestG || (oG == bestG && oj < k2)) { bestG = oG; k2 = oj; }
        }
        float s = 0.f;
        #pragma unroll
        for (int i = 0; i < 10; i++) { l[i] = __expf(l[i] - bestL); s += l[i]; }
        #pragma unroll
        for (int off = 16; off; off >>= 1) s += __shfl_xor_sync(0xffffffffu, s, off);
        float inv = 1.0f / s;
        #pragma unroll
        for (int i = 0; i < 10; i++) sAvg[wid][lane + i * 32] += l[i] * inv;

        if (lane == 0)
            atomicAdd(&g_counts[((n & (NT - 1)) * NG + g) * NV + k1], 1.0f);

        float4 cb = ((const float4*)(codebook + (size_t)(g * NV + k2) * ND))[lane];
        ((float4*)(out + (size_t)n * (NG * ND) + g * ND))[lane] = cb;
    }

    __syncthreads();
    for (int x = tid; x < NG * NV; x += 256) {
        int gg = x / NV, v = x - gg * NV;
        float s = sAvg[gg][v] + sAvg[gg + 2][v] + sAvg[gg + 4][v] + sAvg[gg + 6][v];
        atomicAdd(&g_avg[x], s);
    }
}

// ---------------- perplexity reduction (proven in R2) ----------------
__global__ __launch_bounds__(320) void perp_kernel(int mode, float scale, float* __restrict__ out) {
    const float* vals = (mode == 0) ? g_counts : g_avg;
    const int tid = threadIdx.x;
    float p = vals[(size_t)blockIdx.x * NV + tid] * scale;
    float term = p * logf(p + 1e-7f);
    #pragma unroll
    for (int off = 16; off; off >>= 1) term += __shfl_xor_sync(0xffffffffu, term, off);
    __shared__ float red[10];
    if ((tid & 31) == 0) red[tid >> 5] = term;
    __syncthreads();
    if (tid == 0) {
        float s2 = red[0];
        #pragma unroll
        for (int i = 1; i < 10; i++) s2 += red[i];
        atomicAdd(out + mode, expf(-s2));
    }
}

// ---------------- launch ----------------
extern "C" void kernel_launch(void* const* d_in, const int* in_sizes, int n_in,
                              void* d_out, int out_size)
{
    const float* x        = (const float*)d_in[0];  // (16,1024,512)
    const float* w_proj   = (const float*)d_in[1];  // (640,512)
    const float* b_proj   = (const float*)d_in[2];  // (640)
    const float* codebook = (const float*)d_in[3];  // (1,640,128)
    const float* gumbel   = (const float*)d_in[4];  // (16384,2,320)
    float* out = (float*)d_out;
    float* scalars = out + (out_size - 2);

    static int smem_set = 0;
    if (!smem_set) {
        cudaFuncSetAttribute(gemm_mma_kernel, cudaFuncAttributeMaxDynamicSharedMemorySize, GEMM_SMEM);
        smem_set = 1;
    }

    zero_kernel<<<(NT * NG * NV + 255) / 256, 256>>>(scalars);

    split_kernel<<<(NTOK * NF / 4 + 255) / 256, 256>>>((const float4*)x, NTOK * NF / 4, 0);
    split_kernel<<<(NJ * NF / 4 + 255) / 256, 256>>>((const float4*)w_proj, NJ * NF / 4, 1);

    dim3 ggrid(NJ / 64, NTOK / 128);   // (10, 128)
    gemm_mma_kernel<<<ggrid, 256, GEMM_SMEM>>>(b_proj);

    epilogue_kernel<<<256, 256>>>(gumbel, codebook, out);

    perp_kernel<<<NT * NG, 320>>>(0, 1.0f / NB, scalars);
    perp_kernel<<<NG, 320>>>(1, 1.0f / (float)NTOK, scalars);
}

// round 5
// speedup vs baseline: 1.9070x; 1.0529x over previous
#include <cuda_runtime.h>
#include <cuda_fp16.h>
#include <cstdint>

// ---------------- problem constants ----------------
#define NB 16
#define NT 1024
#define NF 512
#define NG 2
#define NV 320
#define ND 128
#define NTOK (NB*NT)        // 16384
#define NJ (NG*NV)          // 640

// ---------------- device scratch (no cudaMalloc allowed) ----------------
__device__ __half g_x0[(size_t)NTOK * NF];   // 16 MB
__device__ __half g_x1[(size_t)NTOK * NF];   // 16 MB
__device__ __half g_w0[(size_t)NJ * NF];
__device__ __half g_w1[(size_t)NJ * NF];
__device__ float g_logits[(size_t)NTOK * NJ];  // 40 MB
__device__ float g_counts[NT * NG * NV];
__device__ float g_avg[NG * NV];

// ---------------- helpers ----------------
__device__ __forceinline__ uint32_t smem_u32(const void* p) {
    uint32_t a;
    asm("{ .reg .u64 t; cvta.to.shared.u64 t, %1; cvt.u32.u64 %0, t; }" : "=r"(a) : "l"(p));
    return a;
}
#define SW128(b) ((b) ^ (((b) >> 3) & 0x70))
#define CP_ASYNC16(s, g) \
    asm volatile("cp.async.cg.shared.global [%0], [%1], 16;" :: "r"(s), "l"(g))
#define CP_COMMIT() asm volatile("cp.async.commit_group;" ::: "memory")
#define CP_WAIT(n)  asm volatile("cp.async.wait_group %0;" :: "n"(n) : "memory")
#define LDSM_X4(r0, r1, r2, r3, addr) \
    asm volatile("ldmatrix.sync.aligned.m8n8.x4.shared.b16 {%0,%1,%2,%3}, [%4];" \
        : "=r"(r0), "=r"(r1), "=r"(r2), "=r"(r3) : "r"(addr))
#define MMA16816(c, a0, a1, a2, a3, b0, b1) \
    asm volatile("mma.sync.aligned.m16n8k16.row.col.f32.f16.f16.f32 " \
        "{%0,%1,%2,%3}, {%4,%5,%6,%7}, {%8,%9}, {%0,%1,%2,%3};" \
        : "+f"((c)[0]), "+f"((c)[1]), "+f"((c)[2]), "+f"((c)[3]) \
        : "r"(a0), "r"(a1), "r"(a2), "r"(a3), "r"(b0), "r"(b1))

// ---------------- zero kernel ----------------
__global__ void zero_kernel(float* out_scalars) {
    int i = blockIdx.x * blockDim.x + threadIdx.x;
    if (i < NT * NG * NV) g_counts[i] = 0.f;
    if (i < NG * NV) g_avg[i] = 0.f;
    if (i < 2) out_scalars[i] = 0.f;
}

// ---------------- fp32 -> fp16 two-term split (x and w in one launch) ----------------
#define X4 (NTOK * NF / 4)   // 2097152
#define W4 (NJ * NF / 4)     // 81920
__global__ __launch_bounds__(256) void split_kernel(
    const float4* __restrict__ xs, const float4* __restrict__ ws)
{
    int i = blockIdx.x * blockDim.x + threadIdx.x;
    const float4* src; __half2 *d0, *d1; int idx;
    if (i < X4) { src = xs; d0 = (__half2*)g_x0; d1 = (__half2*)g_x1; idx = i; }
    else if (i < X4 + W4) { src = ws; d0 = (__half2*)g_w0; d1 = (__half2*)g_w1; idx = i - X4; }
    else return;
    float4 v = src[idx];
    __half hx = __float2half_rn(v.x), hy = __float2half_rn(v.y);
    __half hz = __float2half_rn(v.z), hw = __float2half_rn(v.w);
    float rx = v.x - __half2float(hx), ry = v.y - __half2float(hy);
    float rz = v.z - __half2float(hz), rw = v.w - __half2float(hw);
    d0[2*idx]   = __halves2half2(hx, hy);
    d0[2*idx+1] = __halves2half2(hz, hw);
    d1[2*idx]   = __halves2half2(__float2half_rn(rx), __float2half_rn(ry));
    d1[2*idx+1] = __halves2half2(__float2half_rn(rz), __float2half_rn(rw));
}

// ---------------- HMMA GEMM: logits = x*W^T + b via 3-pass fp16 split ----------------
// BM=128 BN=64 BK=64(half). 128 threads / 4 warps, warp tile 64x32.
// 3-stage cp.async pipeline, SW128 swizzle. 3 CTAs/SM (216KB smem).
#define STAGES 3
#define STG_A 16384                 // 128 rows x 128B
#define STG_B 8192                  // 64 rows x 128B
#define STG_BYTES (STG_A + STG_B)   // 24576
#define GEMM_SMEM (STAGES * STG_BYTES)   // 73728

__global__ __launch_bounds__(128, 3) void gemm_mma_kernel(const float* __restrict__ bias)
{
    extern __shared__ __align__(1024) char smem[];
    const uint32_t sb = smem_u32(smem);
    const int tid = threadIdx.x, lane = tid & 31, wid = tid >> 5;
    const int wm = (wid & 1) * 64;       // warp m offset (64-row tile)
    const int wn = (wid >> 1) * 32;      // warp n offset (32-col tile)
    const int m0 = blockIdx.y * 128;
    const int j0 = blockIdx.x * 64;

    float acc[4][4][4];                  // [mt 16-row][nt 8-col][4]
    #pragma unroll
    for (int mt = 0; mt < 4; mt++)
        #pragma unroll
        for (int nt = 0; nt < 4; nt++)
            #pragma unroll
            for (int c = 0; c < 4; c++) acc[mt][nt][c] = 0.f;

    // ---- stage loader: 128 threads, A 1024 chunks (8/thr), B 512 chunks (4/thr) ----
    auto load_stage = [&](int s, int it) {
        const __half* Ag = (it < 16) ? g_x0 : g_x1;
        const __half* Bg = (it >= 8 && it < 16) ? g_w1 : g_w0;
        const int kk = (it & 7) * 64;
        const uint32_t stA = sb + s * STG_BYTES;
        const uint32_t stB = stA + STG_A;
        #pragma unroll
        for (int n = 0; n < 8; n++) {
            int i = tid + n * 128;
            int r = i >> 3, u = i & 7;
            CP_ASYNC16(stA + SW128(r * 128 + u * 16),
                       (const void*)(Ag + (size_t)(m0 + r) * NF + kk + u * 8));
        }
        #pragma unroll
        for (int n = 0; n < 4; n++) {
            int i = tid + n * 128;
            int r = i >> 3, u = i & 7;
            CP_ASYNC16(stB + SW128(r * 128 + u * 16),
                       (const void*)(Bg + (size_t)(j0 + r) * NF + kk + u * 8));
        }
        CP_COMMIT();
    };

    load_stage(0, 0);
    load_stage(1, 1);

    for (int it = 0; it < 24; it++) {
        CP_WAIT(1);
        __syncthreads();
        const int s = it % STAGES;
        const uint32_t stA = sb + s * STG_BYTES;
        const uint32_t stB = stA + STG_A;
        #pragma unroll
        for (int ks = 0; ks < 4; ks++) {
            uint32_t a[4][4], b[2][4];
            #pragma unroll
            for (int mt = 0; mt < 4; mt++) {
                uint32_t off = (uint32_t)(wm + mt * 16 + (lane & 15)) * 128 + ks * 32 + (lane >> 4) * 16;
                LDSM_X4(a[mt][0], a[mt][1], a[mt][2], a[mt][3], stA + SW128(off));
            }
            #pragma unroll
            for (int nb = 0; nb < 2; nb++) {
                uint32_t off = (uint32_t)(wn + nb * 16 + (lane & 15)) * 128 + ks * 32 + (lane >> 4) * 16;
                LDSM_X4(b[nb][0], b[nb][1], b[nb][2], b[nb][3], stB + SW128(off));
            }
            #pragma unroll
            for (int mt = 0; mt < 4; mt++)
                #pragma unroll
                for (int nt = 0; nt < 4; nt++)
                    MMA16816(acc[mt][nt], a[mt][0], a[mt][1], a[mt][2], a[mt][3],
                             b[nt >> 1][nt & 1], b[nt >> 1][(nt & 1) + 2]);
        }
        __syncthreads();
        if (it + 2 < 24) load_stage((it + 2) % STAGES, it + 2);
    }

    // ---- store: add bias, write logits ----
    #pragma unroll
    for (int mt = 0; mt < 4; mt++) {
        #pragma unroll
        for (int nt = 0; nt < 4; nt++) {
            int row = m0 + wm + mt * 16 + (lane >> 2);
            int col = j0 + wn + nt * 8 + (lane & 3) * 2;
            float2 bv = *(const float2*)(bias + col);
            float2 o0 = make_float2(acc[mt][nt][0] + bv.x, acc[mt][nt][1] + bv.y);
            float2 o1 = make_float2(acc[mt][nt][2] + bv.x, acc[mt][nt][3] + bv.y);
            *(float2*)(g_logits + (size_t)row * NJ + col) = o0;
            *(float2*)(g_logits + (size_t)(row + 8) * NJ + col) = o1;
        }
    }
}

// ---------------- fused epilogue (proven) ----------------
__global__ __launch_bounds__(256) void epilogue_kernel(
    const float* __restrict__ gumbel, const float* __restrict__ codebook,
    float* __restrict__ out)
{
    __shared__ float sAvg[8][NV];

    const int tid = threadIdx.x;
    const int wid = tid >> 5;
    const int lane = tid & 31;
    const int g = wid & 1;

    for (int i = tid; i < 8 * NV; i += 256) ((float*)sAvg)[i] = 0.f;
    __syncthreads();

    for (int it = 0; it < 16; it++) {
        int task = blockIdx.x * 128 + it * 8 + wid;
        int n = task >> 1;
        const float* lrow = g_logits + (size_t)n * NJ + g * NV;
        const float* grow = gumbel  + (size_t)n * NJ + g * NV;

        float l[10];
        float bestL = -3.402823466e38f; int k1 = 0;
        float bestG = -3.402823466e38f; int k2 = 0;
        #pragma unroll
        for (int i = 0; i < 10; i++) {
            int v = lane + i * 32;
            float lv = lrow[v];
            l[i] = lv;
            float lg = lv + grow[v];
            if (lv > bestL) { bestL = lv; k1 = v; }
            if (lg > bestG) { bestG = lg; k2 = v; }
        }
        #pragma unroll
        for (int off = 16; off; off >>= 1) {
            float oL = __shfl_xor_sync(0xffffffffu, bestL, off);
            int   oi = __shfl_xor_sync(0xffffffffu, k1,   off);
            if (oL > bestL || (oL == bestL && oi < k1)) { bestL = oL; k1 = oi; }
            float oG = __shfl_xor_sync(0xffffffffu, bestG, off);
            int   oj = __shfl_xor_sync(0xffffffffu, k2,   off);
            if (oG > bestG || (oG == bestG && oj < k2)) { bestG = oG; k2 = oj; }
        }
        float s = 0.f;
        #pragma unroll
        for (int i = 0; i < 10; i++) { l[i] = __expf(l[i] - bestL); s += l[i]; }
        #pragma unroll
        for (int off = 16; off; off >>= 1) s += __shfl_xor_sync(0xffffffffu, s, off);
        float inv = 1.0f / s;
        #pragma unroll
        for (int i = 0; i < 10; i++) sAvg[wid][lane + i * 32] += l[i] * inv;

        if (lane == 0)
            atomicAdd(&g_counts[((n & (NT - 1)) * NG + g) * NV + k1], 1.0f);

        float4 cb = ((const float4*)(codebook + (size_t)(g * NV + k2) * ND))[lane];
        ((float4*)(out + (size_t)n * (NG * ND) + g * ND))[lane] = cb;
    }

    __syncthreads();
    for (int x = tid; x < NG * NV; x += 256) {
        int gg = x / NV, v = x - gg * NV;
        float s = sAvg[gg][v] + sAvg[gg + 2][v] + sAvg[gg + 4][v] + sAvg[gg + 6][v];
        atomicAdd(&g_avg[x], s);
    }
}

// ---------------- perplexity reduction (proven) ----------------
__global__ __launch_bounds__(320) void perp_kernel(int mode, float scale, float* __restrict__ out) {
    const float* vals = (mode == 0) ? g_counts : g_avg;
    const int tid = threadIdx.x;
    float p = vals[(size_t)blockIdx.x * NV + tid] * scale;
    float term = p * logf(p + 1e-7f);
    #pragma unroll
    for (int off = 16; off; off >>= 1) term += __shfl_xor_sync(0xffffffffu, term, off);
    __shared__ float red[10];
    if ((tid & 31) == 0) red[tid >> 5] = term;
    __syncthreads();
    if (tid == 0) {
        float s2 = red[0];
        #pragma unroll
        for (int i = 1; i < 10; i++) s2 += red[i];
        atomicAdd(out + mode, expf(-s2));
    }
}

// ---------------- launch ----------------
extern "C" void kernel_launch(void* const* d_in, const int* in_sizes, int n_in,
                              void* d_out, int out_size)
{
    const float* x        = (const float*)d_in[0];  // (16,1024,512)
    const float* w_proj   = (const float*)d_in[1];  // (640,512)
    const float* b_proj   = (const float*)d_in[2];  // (640)
    const float* codebook = (const float*)d_in[3];  // (1,640,128)
    const float* gumbel   = (const float*)d_in[4];  // (16384,2,320)
    float* out = (float*)d_out;
    float* scalars = out + (out_size - 2);

    cudaFuncSetAttribute(gemm_mma_kernel, cudaFuncAttributeMaxDynamicSharedMemorySize, GEMM_SMEM);

    zero_kernel<<<(NT * NG * NV + 255) / 256, 256>>>(scalars);

    split_kernel<<<(X4 + W4 + 255) / 256, 256>>>((const float4*)x, (const float4*)w_proj);

    dim3 ggrid(NJ / 64, NTOK / 128);   // (10, 128) = 1280 CTAs
    gemm_mma_kernel<<<ggrid, 128, GEMM_SMEM>>>(b_proj);

    epilogue_kernel<<<256, 256>>>(gumbel, codebook, out);

    perp_kernel<<<NT * NG, 320>>>(0, 1.0f / NB, scalars);
    perp_kernel<<<NG, 320>>>(1, 1.0f / (float)NTOK, scalars);
}